// round 6
// baseline (speedup 1.0000x reference)
#include <cuda_runtime.h>
#include <cuda_bf16.h>

// LIF spike scan: x [B=32, T=16, C=128, H=32, W=32] fp32 -> spikes (fp32, same shape).
// Per site: mem = mem*TAU + x_t; s = (mem >= THRESH); mem = (1-s)*mem.
//
// HBM-bound: 512 MiB irreducible traffic; five structural variants all
// saturate ~6.4 TB/s (practical mixed R/W HBM3e wall). R6 = R5 structure
// (16 streaming loads batched, register scan, 16 streaming stores; constant
// shapes, 32-bit indexing) + block=512 for coarser per-CTA DRAM row locality
// (8 KiB contiguous per timestep per CTA instead of 4 KiB).

#define LIF_T      16
#define LIF_THRESH 0.5f
#define LIF_TAU    0.25f
#define LIF_CHW4   32768           // C*H*W/4 = 128*32*32/4 (compile-time)

__global__ __launch_bounds__(512) void lif_spike_kernel(
    const float4* __restrict__ x,   // [B, T, CHW/4] viewed as float4
    float4* __restrict__ out)
{
    // gid in [0, B*CHW4) = [0, 1048576); all indices fit 32-bit.
    unsigned gid = blockIdx.x * blockDim.x + threadIdx.x;
    unsigned b   = gid >> 15;              // gid / LIF_CHW4
    unsigned sp  = gid & (LIF_CHW4 - 1);   // gid % LIF_CHW4

    // float4 offset of (b, t=0, sp); max = 2^24, fits 32-bit.
    unsigned base = b * (LIF_T * LIF_CHW4) + sp;

    // All 16 time-step loads are independent; streaming (evict-first).
    float4 v[LIF_T];
#pragma unroll
    for (int t = 0; t < LIF_T; t++) {
        v[t] = __ldcs(&x[base + t * LIF_CHW4]);
    }

    // Sequential LIF scan in registers, 4 lanes in parallel.
    float4 mem = make_float4(0.f, 0.f, 0.f, 0.f);
#pragma unroll
    for (int t = 0; t < LIF_T; t++) {
        mem.x = fmaf(mem.x, LIF_TAU, v[t].x);
        mem.y = fmaf(mem.y, LIF_TAU, v[t].y);
        mem.z = fmaf(mem.z, LIF_TAU, v[t].z);
        mem.w = fmaf(mem.w, LIF_TAU, v[t].w);

        float sx = (mem.x >= LIF_THRESH) ? 1.f : 0.f;
        float sy = (mem.y >= LIF_THRESH) ? 1.f : 0.f;
        float sz = (mem.z >= LIF_THRESH) ? 1.f : 0.f;
        float sw = (mem.w >= LIF_THRESH) ? 1.f : 0.f;

        // hard reset
        mem.x = (sx != 0.f) ? 0.f : mem.x;
        mem.y = (sy != 0.f) ? 0.f : mem.y;
        mem.z = (sz != 0.f) ? 0.f : mem.z;
        mem.w = (sw != 0.f) ? 0.f : mem.w;

        v[t] = make_float4(sx, sy, sz, sw);   // reuse v[] as output buffer
    }

#pragma unroll
    for (int t = 0; t < LIF_T; t++) {
        __stcs(&out[base + t * LIF_CHW4], v[t]);
    }
}

extern "C" void kernel_launch(void* const* d_in, const int* in_sizes, int n_in,
                              void* d_out, int out_size)
{
    const float* x = (const float*)d_in[0];
    float* out = (float*)d_out;

    // x: [32, 16, 128, 32, 32]; n_sites = 32 * 32768 = 1,048,576 float4 sites.
    const int chw  = 128 * 32 * 32;
    const int B    = in_sizes[0] / (LIF_T * chw);   // 32
    const int n_sites = B * LIF_CHW4;               // 1,048,576

    const int threads = 512;
    const int blocks = n_sites / threads;           // 2048, exact

    lif_spike_kernel<<<blocks, threads>>>((const float4*)x, (float4*)out);
}